// round 3
// baseline (speedup 1.0000x reference)
#include <cuda_runtime.h>
#include <cstdint>
#include <cstddef>

#define B_ 8
#define N_ 36720
#define PC 85
#define KCAND 512
#define MAXDET 300
#define CAP 4096
#define NBINS 4096
#define CONF_T 0.596f
#define IOU_T 0.45f
#define MAX_WH_ 4096.0f

// ---------------- scratch (device globals; no allocation allowed) ----------
__device__ float g_score[B_ * N_];
__device__ int   g_cls[B_ * N_];
__device__ int   g_hist[B_ * NBINS];
__device__ int   g_ccount[B_];
__device__ int   g_T1[B_];
__device__ unsigned long long g_cand[B_ * CAP];
__device__ float g_sc[B_ * KCAND];
__device__ int   g_idx[B_ * KCAND];
__device__ float g_det[B_ * MAXDET * 4];
__device__ int   g_num[B_];
// transposed feature maps: [B][H*W][C]
__device__ float g_t1[(size_t)B_ * 96 * 96 * 128];
__device__ float g_t2[(size_t)B_ * 48 * 48 * 256];
__device__ float g_t3[(size_t)B_ * 24 * 24 * 512];
__device__ float g_t4[(size_t)B_ * 12 * 12 * 1024];

// ---------------- init: zero histograms & counters --------------------------
__global__ void k_init() {
    int t = blockIdx.x * blockDim.x + threadIdx.x;
    if (t < B_ * NBINS) g_hist[t] = 0;
    if (t < B_) g_ccount[t] = 0;
}

// ---------------- score: warp per candidate ---------------------------------
__global__ void k_score(const float* __restrict__ preds) {
    int gw = (blockIdx.x * blockDim.x + threadIdx.x) >> 5;
    int lane = threadIdx.x & 31;
    if (gw >= B_ * N_) return;
    const float* row = preds + (size_t)gw * PC;
    float v0 = row[lane];
    float v1 = row[lane + 32];
    float v2 = (lane + 64 < PC) ? row[lane + 64] : -1.0f;
    float obj = __shfl_sync(0xffffffffu, v0, 4);

    float bv = -1.0f; int bc = 1 << 30;
    if (lane >= 5) { float cv = v0 * obj; if (cv > bv) { bv = cv; bc = lane; } }
    { float cv = v1 * obj; int col = lane + 32;
      if (cv > bv || (cv == bv && col < bc)) { bv = cv; bc = col; } }
    if (lane + 64 < PC) { float cv = v2 * obj; int col = lane + 64;
      if (cv > bv || (cv == bv && col < bc)) { bv = cv; bc = col; } }
#pragma unroll
    for (int o = 16; o > 0; o >>= 1) {
        float ov = __shfl_down_sync(0xffffffffu, bv, o);
        int   oc = __shfl_down_sync(0xffffffffu, bc, o);
        if (ov > bv || (ov == bv && oc < bc)) { bv = ov; bc = oc; }
    }
    if (lane == 0) {
        float conf = bv;
        bool valid = (obj > CONF_T) && (conf > CONF_T);
        float sc = valid ? conf : 0.0f;
        g_score[gw] = sc;
        g_cls[gw] = bc - 5;
        if (sc > 0.0f) {
            int b = gw / N_;
            int bin = min(NBINS - 1, (int)(sc * 4096.0f));
            atomicAdd(&g_hist[b * NBINS + bin], 1);
        }
    }
}

// ---------------- select threshold bin --------------------------------------
__global__ void k_select() {
    int b = threadIdx.x;
    if (b >= B_) return;
    int cum = 0, t1 = 0;
    for (int bin = NBINS - 1; bin >= 0; --bin) {
        cum += g_hist[b * NBINS + bin];
        if (cum >= KCAND) { t1 = bin; break; }
    }
    g_T1[b] = t1;
}

// ---------------- compact candidates >= threshold bin -----------------------
__global__ void k_compact() {
    int t = blockIdx.x * blockDim.x + threadIdx.x;
    if (t >= B_ * N_) return;
    float sc = g_score[t];
    if (sc <= 0.0f) return;
    int b = t / N_;
    int bin = min(NBINS - 1, (int)(sc * 4096.0f));
    if (bin >= g_T1[b]) {
        int pos = atomicAdd(&g_ccount[b], 1);
        if (pos < CAP) {
            unsigned key = __float_as_uint(sc);
            int i = t - b * N_;
            g_cand[b * CAP + pos] =
                ((unsigned long long)key << 32) | (unsigned)(0xFFFFFFFFu - (unsigned)i);
        }
    }
}

// ---------------- exact sort of compacted set (bitonic, desc, stable) -------
__global__ void k_sort() {
    __shared__ unsigned long long keys[CAP];
    int b = blockIdx.x, tid = threadIdx.x;
    int C = g_ccount[b]; if (C > CAP) C = CAP;
    for (int s = tid; s < CAP; s += 1024)
        keys[s] = (s < C) ? g_cand[b * CAP + s] : 0ULL;
    __syncthreads();
    for (int k = 2; k <= CAP; k <<= 1) {
        for (int jj = k >> 1; jj > 0; jj >>= 1) {
            for (int p = tid; p < CAP / 2; p += 1024) {
                int i = ((p & ~(jj - 1)) << 1) | (p & (jj - 1));
                int l = i + jj;
                bool dirDesc = ((i & k) == 0);
                unsigned long long a = keys[i], c = keys[l];
                bool sw = dirDesc ? (a < c) : (a > c);
                if (sw) { keys[i] = c; keys[l] = a; }
            }
            __syncthreads();
        }
    }
    if (tid < KCAND) {
        unsigned long long kk = keys[tid];
        if (kk == 0ULL) { g_sc[b * KCAND + tid] = 0.0f; g_idx[b * KCAND + tid] = 0; }
        else {
            g_sc[b * KCAND + tid] = __uint_as_float((unsigned)(kk >> 32));
            g_idx[b * KCAND + tid] = (int)(0xFFFFFFFFu - (unsigned)kk);
        }
    }
}

// ---------------- greedy NMS + compact kept to detections -------------------
__global__ void k_nms(const float* __restrict__ preds) {
    __shared__ float ox1[KCAND], oy1[KCAND], ox2[KCAND], oy2[KCAND], oar[KCAND];
    __shared__ float rbx[KCAND * 4];
    __shared__ int keep[KCAND];
    __shared__ int rank[KCAND];
    int b = blockIdx.x, j = threadIdx.x;

    float sc = g_sc[b * KCAND + j];
    int kp = (sc > 0.0f) ? 1 : 0;
    if (kp) {
        int idx = g_idx[b * KCAND + j];
        const float* row = preds + ((size_t)b * N_ + idx) * PC;
        float x = row[0], y = row[1], w = row[2], h = row[3];
        int cls = g_cls[b * N_ + idx];
        float off = (float)cls * MAX_WH_;
        float x1 = x - w / 2.0f, y1 = y - h / 2.0f;
        float x2 = x + w / 2.0f, y2 = y + h / 2.0f;
        rbx[j * 4 + 0] = x1; rbx[j * 4 + 1] = y1;
        rbx[j * 4 + 2] = x2; rbx[j * 4 + 3] = y2;
        float a1 = x1 + off, c1 = y1 + off, a2 = x2 + off, c2 = y2 + off;
        ox1[j] = a1; oy1[j] = c1; ox2[j] = a2; oy2[j] = c2;
        oar[j] = (a2 - a1) * (c2 - c1);
    }
    keep[j] = kp;
    __syncthreads();

    for (int i = 0; i < KCAND - 1; i++) {
        if (keep[i]) {
            if (j > i && keep[j]) {
                float xx1 = fmaxf(ox1[i], ox1[j]);
                float yy1 = fmaxf(oy1[i], oy1[j]);
                float xx2 = fminf(ox2[i], ox2[j]);
                float yy2 = fminf(oy2[i], oy2[j]);
                float iw = fmaxf(xx2 - xx1, 0.0f);
                float ih = fmaxf(yy2 - yy1, 0.0f);
                float inter = iw * ih;
                float iou = inter / (oar[i] + oar[j] - inter + 1e-7f);
                if (iou > IOU_T) keep[j] = 0;
            }
        }
        __syncthreads();
    }

    if (j == 0) {
        int cnt = 0;
        for (int t = 0; t < KCAND; t++) {
            if (keep[t]) { rank[t] = (cnt < MAXDET) ? cnt : -1; cnt++; }
            else rank[t] = -1;
        }
        g_num[b] = (cnt < MAXDET) ? cnt : MAXDET;
    }
    __syncthreads();
    int r = rank[j];
    if (r >= 0) {
        g_det[(b * MAXDET + r) * 4 + 0] = rbx[j * 4 + 0];
        g_det[(b * MAXDET + r) * 4 + 1] = rbx[j * 4 + 1];
        g_det[(b * MAXDET + r) * 4 + 2] = rbx[j * 4 + 2];
        g_det[(b * MAXDET + r) * 4 + 3] = rbx[j * 4 + 3];
    }
}

// ---------------- tiled transpose [B][C][HW] -> [B][HW][C] ------------------
__global__ void k_transpose(const float* __restrict__ in, int level, int C, int HW) {
    float* out = (level == 0) ? g_t1 : (level == 1) ? g_t2 : (level == 2) ? g_t3 : g_t4;
    __shared__ float tile[32][33];
    int b = blockIdx.z;
    int hw0 = blockIdx.x * 32, c0 = blockIdx.y * 32;
    int tx = threadIdx.x, ty = threadIdx.y;
    int c = c0 + ty, hw = hw0 + tx;
    if (c < C && hw < HW)
        tile[ty][tx] = in[((size_t)b * C + c) * HW + hw];
    __syncthreads();
    int hw2 = hw0 + ty, c2 = c0 + tx;
    if (hw2 < HW && c2 < C)
        out[((size_t)b * HW + hw2) * C + c2] = tile[tx][ty];
}

// ---------------- ROI align (1x1, 2x2 samples) + MLP, 4 rois/block ----------
__global__ void k_roi(const float* __restrict__ W1, const float* __restrict__ b1,
                      const float* __restrict__ W2, const float* __restrict__ b2,
                      float* __restrict__ out) {
    __shared__ float fbuf[4][1920];
    __shared__ float h1[4][64];
    __shared__ float partial[2][4][64];
    __shared__ float swt[4][4][16];
    __shared__ int   soff[4][4][16];
    __shared__ float sbox[4][4];
    __shared__ int   svalid[4];
    __shared__ int   snum;

    int tid = threadIdx.x;
    int b = blockIdx.x / 75;
    int g0 = (blockIdx.x % 75) * 4;

    if (tid == 0) snum = g_num[b];
    __syncthreads();
    if (tid < 4) {
        int r = g0 + tid;
        int v = (r < snum) ? 1 : 0;
        svalid[tid] = v;
#pragma unroll
        for (int c = 0; c < 4; c++)
            sbox[tid][c] = v ? g_det[(b * MAXDET + r) * 4 + c] : 0.0f;
    }
    __syncthreads();

    if (tid < 64) {
        int r = tid >> 4, l = (tid >> 2) & 3, s = tid & 3;
        const float scl[4] = {0.125f, 0.0625f, 0.03125f, 0.015625f};
        const int LH4[4] = {96, 48, 24, 12};
        const int LC4[4] = {128, 256, 512, 1024};
        float sca = scl[l];
        int H = LH4[l], W = LH4[l], C = LC4[l];
        float x1 = sbox[r][0] * sca, y1 = sbox[r][1] * sca;
        float x2 = sbox[r][2] * sca, y2 = sbox[r][3] * sca;
        float rw = fmaxf(x2 - x1, 1.0f), rh = fmaxf(y2 - y1, 1.0f);
        float offy = (s & 2) ? 0.75f : 0.25f;
        float offx = (s & 1) ? 0.75f : 0.25f;
        float yy = y1 + rh * offy;
        float xx = x1 + rw * offx;
        bool valid = (yy > -1.0f) && (yy < (float)H) && (xx > -1.0f) && (xx < (float)W);
        float yc = fmaxf(yy, 0.0f), xc = fmaxf(xx, 0.0f);
        int y0 = (int)fminf(floorf(yc), (float)(H - 1));
        int x0 = (int)fminf(floorf(xc), (float)(W - 1));
        int y1i = min(y0 + 1, H - 1);
        int x1i = min(x0 + 1, W - 1);
        float ly = yc - (float)y0, lx = xc - (float)x0;
        float hy = 1.0f - ly, hx = 1.0f - lx;
        float m = valid ? 0.25f : 0.0f;
        swt[r][l][s * 4 + 0] = hy * hx * m; soff[r][l][s * 4 + 0] = (y0 * W + x0) * C;
        swt[r][l][s * 4 + 1] = hy * lx * m; soff[r][l][s * 4 + 1] = (y0 * W + x1i) * C;
        swt[r][l][s * 4 + 2] = ly * hx * m; soff[r][l][s * 4 + 2] = (y1i * W + x0) * C;
        swt[r][l][s * 4 + 3] = ly * lx * m; soff[r][l][s * 4 + 3] = (y1i * W + x1i) * C;
    }
    __syncthreads();

    const int chOff[4] = {0, 128, 384, 896};
    for (int r = 0; r < 4; r++) {
        if (!svalid[r]) continue;
        for (int l = 0; l < 4; l++) {
            int H = (l == 0) ? 96 : (l == 1) ? 48 : (l == 2) ? 24 : 12;
            int C = (l == 0) ? 128 : (l == 1) ? 256 : (l == 2) ? 512 : 1024;
            const float* base =
                ((l == 0) ? g_t1 : (l == 1) ? g_t2 : (l == 2) ? g_t3 : g_t4) +
                (size_t)b * H * H * C;
            for (int c = tid; c < C; c += 128) {
                float acc = 0.0f;
#pragma unroll
                for (int e = 0; e < 16; e++)
                    acc += swt[r][l][e] * base[soff[r][l][e] + c];
                fbuf[r][chOff[l] + c] = acc;
            }
        }
    }
    __syncthreads();

    // mm1: f[4][1920] @ W1[1920][64]
    {
        int j = tid & 63, half = tid >> 6;
        int kb = half * 960;
        float a0 = 0.f, a1 = 0.f, a2 = 0.f, a3 = 0.f;
        for (int k = 0; k < 960; k++) {
            float wv = W1[(size_t)(kb + k) * 64 + j];
            a0 += fbuf[0][kb + k] * wv;
            a1 += fbuf[1][kb + k] * wv;
            a2 += fbuf[2][kb + k] * wv;
            a3 += fbuf[3][kb + k] * wv;
        }
        partial[half][0][j] = a0; partial[half][1][j] = a1;
        partial[half][2][j] = a2; partial[half][3][j] = a3;
    }
    __syncthreads();
    if (tid < 64) {
#pragma unroll
        for (int r = 0; r < 4; r++) {
            float v = partial[0][r][tid] + partial[1][r][tid] + b1[tid];
            h1[r][tid] = (v > 0.0f) ? v : 0.01f * v;
        }
    }
    __syncthreads();
    if (tid < 64) {
#pragma unroll
        for (int r = 0; r < 4; r++) {
            float acc = 0.0f;
            for (int k = 0; k < 64; k++) acc += h1[r][k] * W2[k * 64 + tid];
            float v = acc + b2[tid];
            v = (v > 0.0f) ? v : 0.01f * v;
            out[((size_t)(b * MAXDET + g0 + r)) * 68 + 4 + tid] = svalid[r] ? v : 0.0f;
        }
    }
    if (tid >= 64 && tid < 80) {
        int t = tid - 64; int r = t >> 2, c = t & 3;
        out[((size_t)(b * MAXDET + g0 + r)) * 68 + c] =
            svalid[r] ? (sbox[r][c] / 768.0f) : 0.0f;
    }
}

// ---------------- launcher ---------------------------------------------------
extern "C" void kernel_launch(void* const* d_in, const int* in_sizes, int n_in,
                              void* d_out, int out_size) {
    const float* preds = (const float*)d_in[0];
    const float* f1 = (const float*)d_in[1];
    const float* f2 = (const float*)d_in[2];
    const float* f3 = (const float*)d_in[3];
    const float* f4 = (const float*)d_in[4];
    const float* W1 = (const float*)d_in[5];
    const float* b1 = (const float*)d_in[6];
    const float* W2 = (const float*)d_in[7];
    const float* b2 = (const float*)d_in[8];
    float* out = (float*)d_out;

    k_init<<<(B_ * NBINS + 255) / 256, 256>>>();
    k_score<<<(B_ * N_ * 32 + 255) / 256, 256>>>(preds);

    dim3 tb(32, 32);
    k_transpose<<<dim3(96 * 96 / 32, 128 / 32, B_), tb>>>(f1, 0, 128, 96 * 96);
    k_transpose<<<dim3(48 * 48 / 32, 256 / 32, B_), tb>>>(f2, 1, 256, 48 * 48);
    k_transpose<<<dim3(24 * 24 / 32, 512 / 32, B_), tb>>>(f3, 2, 512, 24 * 24);
    k_transpose<<<dim3((12 * 12 + 31) / 32, 1024 / 32, B_), tb>>>(f4, 3, 1024, 12 * 12);

    k_select<<<1, B_>>>();
    k_compact<<<(B_ * N_ + 255) / 256, 256>>>();
    k_sort<<<B_, 1024>>>();
    k_nms<<<B_, 512>>>(preds);
    k_roi<<<B_ * 75, 128>>>(W1, b1, W2, b2, out);
}

// round 7
// speedup vs baseline: 1.8441x; 1.8441x over previous
#include <cuda_runtime.h>
#include <cstdint>
#include <cstddef>

#define B_ 8
#define N_ 36720
#define PC 85
#define KCAND 512
#define MAXDET 300
#define CAP 4096
#define NBINS 4096
#define CONF_T 0.596f
#define IOU_T 0.45f
#define MAX_WH_ 4096.0f
#define NW 16          // 512 bits = 16 u32 words
#define RPB 8          // rois per block in k_roi
#define NGRP ((MAXDET + RPB - 1) / RPB)   // 38

// ---------------- scratch (device globals; no allocation allowed) ----------
__device__ float g_score[B_ * N_];
__device__ int   g_cls[B_ * N_];
__device__ int   g_hist[B_ * NBINS];
__device__ int   g_ccount[B_];
__device__ int   g_T1[B_];
__device__ unsigned long long g_cand[B_ * CAP];
__device__ float g_sc[B_ * KCAND];
__device__ float g_ox1[B_ * KCAND], g_oy1[B_ * KCAND];
__device__ float g_ox2[B_ * KCAND], g_oy2[B_ * KCAND];
__device__ float g_oar[B_ * KCAND];
__device__ float g_rbx[B_ * KCAND * 4];
__device__ unsigned g_mask[B_ * KCAND * NW];
__device__ float g_det[B_ * MAXDET * 4];
__device__ int   g_num[B_];
__device__ float g_t1[(size_t)B_ * 96 * 96 * 128];
__device__ float g_t2[(size_t)B_ * 48 * 48 * 256];
__device__ float g_t3[(size_t)B_ * 24 * 24 * 512];
__device__ float g_t4[(size_t)B_ * 12 * 12 * 1024];

__global__ void k_init() {
    int t = blockIdx.x * blockDim.x + threadIdx.x;
    if (t < B_ * NBINS) g_hist[t] = 0;
    if (t < B_) g_ccount[t] = 0;
}

__global__ void k_score(const float* __restrict__ preds) {
    int gw = (blockIdx.x * blockDim.x + threadIdx.x) >> 5;
    int lane = threadIdx.x & 31;
    if (gw >= B_ * N_) return;
    const float* row = preds + (size_t)gw * PC;
    float v0 = row[lane];
    float v1 = row[lane + 32];
    float v2 = (lane + 64 < PC) ? row[lane + 64] : -1.0f;
    float obj = __shfl_sync(0xffffffffu, v0, 4);

    float bv = -1.0f; int bc = 1 << 30;
    if (lane >= 5) { float cv = v0 * obj; if (cv > bv) { bv = cv; bc = lane; } }
    { float cv = v1 * obj; int col = lane + 32;
      if (cv > bv || (cv == bv && col < bc)) { bv = cv; bc = col; } }
    if (lane + 64 < PC) { float cv = v2 * obj; int col = lane + 64;
      if (cv > bv || (cv == bv && col < bc)) { bv = cv; bc = col; } }
#pragma unroll
    for (int o = 16; o > 0; o >>= 1) {
        float ov = __shfl_down_sync(0xffffffffu, bv, o);
        int   oc = __shfl_down_sync(0xffffffffu, bc, o);
        if (ov > bv || (ov == bv && oc < bc)) { bv = ov; bc = oc; }
    }
    if (lane == 0) {
        float conf = bv;
        bool valid = (obj > CONF_T) && (conf > CONF_T);
        float sc = valid ? conf : 0.0f;
        g_score[gw] = sc;
        g_cls[gw] = bc - 5;
        if (sc > 0.0f) {
            int b = gw / N_;
            int bin = min(NBINS - 1, (int)(sc * 4096.0f));
            atomicAdd(&g_hist[b * NBINS + bin], 1);
        }
    }
}

__global__ void k_select() {
    int b = threadIdx.x;
    if (b >= B_) return;
    int cum = 0, t1 = 0;
    for (int bin = NBINS - 1; bin >= 0; --bin) {
        cum += g_hist[b * NBINS + bin];
        if (cum >= KCAND) { t1 = bin; break; }
    }
    g_T1[b] = t1;
}

__global__ void k_compact() {
    int t = blockIdx.x * blockDim.x + threadIdx.x;
    if (t >= B_ * N_) return;
    float sc = g_score[t];
    if (sc <= 0.0f) return;
    int b = t / N_;
    int bin = min(NBINS - 1, (int)(sc * 4096.0f));
    if (bin >= g_T1[b]) {
        int pos = atomicAdd(&g_ccount[b], 1);
        if (pos < CAP) {
            unsigned key = __float_as_uint(sc);
            int i = t - b * N_;
            g_cand[b * CAP + pos] =
                ((unsigned long long)key << 32) | (unsigned)(0xFFFFFFFFu - (unsigned)i);
        }
    }
}

__global__ void k_sort(const float* __restrict__ preds) {
    __shared__ unsigned long long keys[CAP];
    int b = blockIdx.x, tid = threadIdx.x;   // 512 threads
    int C = g_ccount[b]; if (C > CAP) C = CAP;
    int P = KCAND; while (P < C) P <<= 1;
    for (int s = tid; s < P; s += 512)
        keys[s] = (s < C) ? g_cand[b * CAP + s] : 0ULL;
    __syncthreads();
    for (int k = 2; k <= P; k <<= 1) {
        for (int jj = k >> 1; jj > 0; jj >>= 1) {
            for (int p = tid; p < (P >> 1); p += 512) {
                int i = ((p & ~(jj - 1)) << 1) | (p & (jj - 1));
                int l = i + jj;
                bool dirDesc = ((i & k) == 0);
                unsigned long long a = keys[i], c = keys[l];
                bool sw = dirDesc ? (a < c) : (a > c);
                if (sw) { keys[i] = c; keys[l] = a; }
            }
            __syncthreads();
        }
    }
    {
        unsigned long long kk = keys[tid];
        float sc; int idx;
        if (kk == 0ULL) { sc = 0.0f; idx = 0; }
        else {
            sc = __uint_as_float((unsigned)(kk >> 32));
            idx = (int)(0xFFFFFFFFu - (unsigned)kk);
        }
        g_sc[b * KCAND + tid] = sc;
        const float* row = preds + ((size_t)b * N_ + idx) * PC;
        float x = row[0], y = row[1], w = row[2], h = row[3];
        int cls = g_cls[b * N_ + idx];
        float off = (float)cls * MAX_WH_;
        float x1 = x - w / 2.0f, y1 = y - h / 2.0f;
        float x2 = x + w / 2.0f, y2 = y + h / 2.0f;
        int gi = b * KCAND + tid;
        g_rbx[gi * 4 + 0] = x1; g_rbx[gi * 4 + 1] = y1;
        g_rbx[gi * 4 + 2] = x2; g_rbx[gi * 4 + 3] = y2;
        float a1 = x1 + off, c1 = y1 + off, a2 = x2 + off, c2 = y2 + off;
        g_ox1[gi] = a1; g_oy1[gi] = c1; g_ox2[gi] = a2; g_oy2[gi] = c2;
        g_oar[gi] = (a2 - a1) * (c2 - c1);
    }
}

__global__ void k_iou() {
    int gw = (blockIdx.x * blockDim.x + threadIdx.x) >> 5;
    int lane = threadIdx.x & 31;
    if (gw >= B_ * KCAND * NW) return;
    int w = gw & (NW - 1);
    int i = (gw >> 4) & (KCAND - 1);
    int b = gw >> 13;
    int base = b * KCAND;
    int j = w * 32 + lane;
    float ix1 = g_ox1[base + i], iy1 = g_oy1[base + i];
    float ix2 = g_ox2[base + i], iy2 = g_oy2[base + i];
    float iar = g_oar[base + i];
    float jx1 = g_ox1[base + j], jy1 = g_oy1[base + j];
    float jx2 = g_ox2[base + j], jy2 = g_oy2[base + j];
    float jar = g_oar[base + j];
    float xx1 = fmaxf(ix1, jx1);
    float yy1 = fmaxf(iy1, jy1);
    float xx2 = fminf(ix2, jx2);
    float yy2 = fminf(iy2, jy2);
    float iw = fmaxf(xx2 - xx1, 0.0f);
    float ih = fmaxf(yy2 - yy1, 0.0f);
    float inter = iw * ih;
    float iou = inter / (iar + jar - inter + 1e-7f);
    bool bit = (j > i) && (iou > IOU_T);
    unsigned m = __ballot_sync(0xffffffffu, bit);
    if (lane == 0) g_mask[(base + i) * NW + w] = m;
}

__global__ void k_scan() {
    __shared__ unsigned smask[KCAND][NW];
    __shared__ unsigned char sany[KCAND];
    __shared__ int srank[KCAND];
    int b = blockIdx.x, tid = threadIdx.x;   // 512 threads
    unsigned any = 0;
#pragma unroll
    for (int w = 0; w < NW; w++) {
        unsigned m = g_mask[(b * KCAND + tid) * NW + w];
        smask[tid][w] = m; any |= m;
    }
    sany[tid] = any ? 1 : 0;
    srank[tid] = -1;
    __syncthreads();

    if (tid < 32) {
        int lane = tid;
        unsigned rem = 0;
#pragma unroll
        for (int w = 0; w < NW; w++) {
            float scv = g_sc[b * KCAND + w * 32 + lane];
            unsigned vw = __ballot_sync(0xffffffffu, scv > 0.0f);
            if (lane == w) rem = ~vw;
        }
        int cnt = 0;
        for (int i = 0; i < KCAND && cnt < MAXDET; i++) {
            unsigned rw = __shfl_sync(0xffffffffu, rem, i >> 5);
            bool kept = !((rw >> (i & 31)) & 1u);
            if (kept) {
                if (sany[i] && lane < NW) rem |= smask[i][lane];
                if (lane == 0) srank[i] = cnt;
                cnt++;
            }
        }
        if (lane == 0) g_num[b] = cnt;
    }
    __syncthreads();
    int r = srank[tid];
    if (r >= 0 && r < MAXDET) {
        int gi = b * KCAND + tid;
        g_det[(b * MAXDET + r) * 4 + 0] = g_rbx[gi * 4 + 0];
        g_det[(b * MAXDET + r) * 4 + 1] = g_rbx[gi * 4 + 1];
        g_det[(b * MAXDET + r) * 4 + 2] = g_rbx[gi * 4 + 2];
        g_det[(b * MAXDET + r) * 4 + 3] = g_rbx[gi * 4 + 3];
    }
}

__global__ void k_transpose(const float* __restrict__ in, int level, int C, int HW) {
    float* out = (level == 0) ? g_t1 : (level == 1) ? g_t2 : (level == 2) ? g_t3 : g_t4;
    __shared__ float tile[32][33];
    int b = blockIdx.z;
    int hw0 = blockIdx.x * 32, c0 = blockIdx.y * 32;
    int tx = threadIdx.x, ty = threadIdx.y;   // 32 x 8
    const float* inb = in + (size_t)b * C * HW;
    float* outb = out + (size_t)b * HW * C;
    int hw = hw0 + tx;
#pragma unroll
    for (int i = 0; i < 32; i += 8) {
        int c = c0 + ty + i;
        if (hw < HW) tile[ty + i][tx] = inb[(size_t)c * HW + hw];
    }
    __syncthreads();
    int c2 = c0 + tx;
#pragma unroll
    for (int i = 0; i < 32; i += 8) {
        int hw2 = hw0 + ty + i;
        if (hw2 < HW) outb[(size_t)hw2 * C + c2] = tile[tx][ty + i];
    }
}

#define ROI_SMEM_FLOATS (RPB*1920 + 8*RPB*64 + RPB*64 + RPB*4*16 + RPB*4*16 + RPB*4 + RPB + 1)
#define ROI_SMEM_BYTES  (ROI_SMEM_FLOATS * 4)

__global__ void k_roi(const float* __restrict__ W1, const float* __restrict__ b1,
                      const float* __restrict__ W2, const float* __restrict__ b2,
                      float* __restrict__ out) {
    extern __shared__ float4 dynv[];
    float* dyn = (float*)dynv;
    float* fbuf  = dyn;
    float* part  = fbuf + RPB * 1920;
    float* h1    = part + 8 * RPB * 64;
    float* swt   = h1 + RPB * 64;
    int*   soff4 = (int*)(swt + RPB * 4 * 16);
    float* sbox  = (float*)(soff4 + RPB * 4 * 16);
    int*   svalid= (int*)(sbox + RPB * 4);
    int*   snum  = svalid + RPB;

    int tid = threadIdx.x;                      // 128
    int b = blockIdx.x / NGRP;
    int g0 = (blockIdx.x % NGRP) * RPB;

    if (tid == 0) snum[0] = g_num[b];
    __syncthreads();
    if (tid < RPB) svalid[tid] = (g0 + tid < snum[0]) ? 1 : 0;
    if (tid < RPB * 4) {
        int r = tid >> 2, c = tid & 3;
        int rr = g0 + r;
        sbox[r * 4 + c] = (rr < snum[0]) ? g_det[(b * MAXDET + rr) * 4 + c] : 0.0f;
    }
    __syncthreads();

    if (tid < RPB * 16) {
        int r = tid >> 4, l = (tid >> 2) & 3, s = tid & 3;
        const float scl[4] = {0.125f, 0.0625f, 0.03125f, 0.015625f};
        const int LH4[4] = {96, 48, 24, 12};
        const int LC4[4] = {128, 256, 512, 1024};
        float sca = scl[l];
        int H = LH4[l], W = LH4[l], C = LC4[l];
        float x1 = sbox[r * 4 + 0] * sca, y1 = sbox[r * 4 + 1] * sca;
        float x2 = sbox[r * 4 + 2] * sca, y2 = sbox[r * 4 + 3] * sca;
        float rw = fmaxf(x2 - x1, 1.0f), rh = fmaxf(y2 - y1, 1.0f);
        float offy = (s & 2) ? 0.75f : 0.25f;
        float offx = (s & 1) ? 0.75f : 0.25f;
        float yy = y1 + rh * offy;
        float xx = x1 + rw * offx;
        bool valid = (yy > -1.0f) && (yy < (float)H) && (xx > -1.0f) && (xx < (float)W);
        float yc = fmaxf(yy, 0.0f), xc = fmaxf(xx, 0.0f);
        int y0 = (int)fminf(floorf(yc), (float)(H - 1));
        int x0 = (int)fminf(floorf(xc), (float)(W - 1));
        int y1i = min(y0 + 1, H - 1);
        int x1i = min(x0 + 1, W - 1);
        float ly = yc - (float)y0, lx = xc - (float)x0;
        float hy = 1.0f - ly, hx = 1.0f - lx;
        float m = valid ? 0.25f : 0.0f;
        int bi = (r * 4 + l) * 16 + s * 4;
        swt[bi + 0] = hy * hx * m; soff4[bi + 0] = ((y0 * W + x0) * C) >> 2;
        swt[bi + 1] = hy * lx * m; soff4[bi + 1] = ((y0 * W + x1i) * C) >> 2;
        swt[bi + 2] = ly * hx * m; soff4[bi + 2] = ((y1i * W + x0) * C) >> 2;
        swt[bi + 3] = ly * lx * m; soff4[bi + 3] = ((y1i * W + x1i) * C) >> 2;
    }
    __syncthreads();

    for (int r = 0; r < RPB; r++) {
        float4* fb4 = (float4*)(fbuf + r * 1920);
        for (int cg = tid; cg < 480; cg += 128) {
            int l, c4l;
            const float4* base4;
            if (cg < 32)       { l = 0; c4l = cg;
                base4 = (const float4*)(g_t1 + (size_t)b * 96 * 96 * 128); }
            else if (cg < 96)  { l = 1; c4l = cg - 32;
                base4 = (const float4*)(g_t2 + (size_t)b * 48 * 48 * 256); }
            else if (cg < 224) { l = 2; c4l = cg - 96;
                base4 = (const float4*)(g_t3 + (size_t)b * 24 * 24 * 512); }
            else               { l = 3; c4l = cg - 224;
                base4 = (const float4*)(g_t4 + (size_t)b * 12 * 12 * 1024); }
            int bi = (r * 4 + l) * 16;
            float4 acc = make_float4(0.f, 0.f, 0.f, 0.f);
#pragma unroll
            for (int e = 0; e < 16; e++) {
                float wv = swt[bi + e];
                float4 v = base4[soff4[bi + e] + c4l];
                acc.x += wv * v.x; acc.y += wv * v.y;
                acc.z += wv * v.z; acc.w += wv * v.w;
            }
            fb4[cg] = acc;
        }
    }
    __syncthreads();

    {
        int jg = tid & 15;
        int ks = tid >> 4;
        const float4* W14 = (const float4*)W1;
        float4 acc[RPB];
#pragma unroll
        for (int r = 0; r < RPB; r++) acc[r] = make_float4(0.f, 0.f, 0.f, 0.f);
        int k0 = ks * 240;
        for (int k = k0; k < k0 + 240; k++) {
            float4 wv = W14[k * 16 + jg];
#pragma unroll
            for (int r = 0; r < RPB; r++) {
                float a = fbuf[r * 1920 + k];
                acc[r].x += a * wv.x; acc[r].y += a * wv.y;
                acc[r].z += a * wv.z; acc[r].w += a * wv.w;
            }
        }
#pragma unroll
        for (int r = 0; r < RPB; r++) {
            int pi = (ks * RPB + r) * 64 + jg * 4;
            part[pi + 0] = acc[r].x; part[pi + 1] = acc[r].y;
            part[pi + 2] = acc[r].z; part[pi + 3] = acc[r].w;
        }
    }
    __syncthreads();
    if (tid < 64) {
#pragma unroll
        for (int r = 0; r < RPB; r++) {
            float v = b1[tid];
#pragma unroll
            for (int ks = 0; ks < 8; ks++) v += part[(ks * RPB + r) * 64 + tid];
            h1[r * 64 + tid] = (v > 0.0f) ? v : 0.01f * v;
        }
    }
    __syncthreads();
    if (tid < 64) {
        float acc[RPB];
#pragma unroll
        for (int r = 0; r < RPB; r++) acc[r] = b2[tid];
        for (int k = 0; k < 64; k++) {
            float wv = W2[k * 64 + tid];
#pragma unroll
            for (int r = 0; r < RPB; r++) acc[r] += h1[r * 64 + k] * wv;
        }
#pragma unroll
        for (int r = 0; r < RPB; r++) {
            int rr = g0 + r;
            if (rr < MAXDET) {
                float v = acc[r];
                v = (v > 0.0f) ? v : 0.01f * v;
                out[((size_t)(b * MAXDET + rr)) * 68 + 4 + tid] = svalid[r] ? v : 0.0f;
            }
        }
    }
    if (tid >= 64 && tid < 64 + RPB * 4) {
        int t = tid - 64; int r = t >> 2, c = t & 3;
        int rr = g0 + r;
        if (rr < MAXDET)
            out[((size_t)(b * MAXDET + rr)) * 68 + c] =
                svalid[r] ? (sbox[r * 4 + c] / 768.0f) : 0.0f;
    }
}

extern "C" void kernel_launch(void* const* d_in, const int* in_sizes, int n_in,
                              void* d_out, int out_size) {
    const float* preds = (const float*)d_in[0];
    const float* f1 = (const float*)d_in[1];
    const float* f2 = (const float*)d_in[2];
    const float* f3 = (const float*)d_in[3];
    const float* f4 = (const float*)d_in[4];
    const float* W1 = (const float*)d_in[5];
    const float* b1 = (const float*)d_in[6];
    const float* W2 = (const float*)d_in[7];
    const float* b2 = (const float*)d_in[8];
    float* out = (float*)d_out;

    cudaFuncSetAttribute(k_roi, cudaFuncAttributeMaxDynamicSharedMemorySize,
                         ROI_SMEM_BYTES);

    k_init<<<(B_ * NBINS + 255) / 256, 256>>>();
    k_score<<<(B_ * N_ * 32 + 255) / 256, 256>>>(preds);

    dim3 tb(32, 8);
    k_transpose<<<dim3(96 * 96 / 32, 128 / 32, B_), tb>>>(f1, 0, 128, 96 * 96);
    k_transpose<<<dim3(48 * 48 / 32, 256 / 32, B_), tb>>>(f2, 1, 256, 48 * 48);
    k_transpose<<<dim3(24 * 24 / 32, 512 / 32, B_), tb>>>(f3, 2, 512, 24 * 24);
    k_transpose<<<dim3((144 + 31) / 32, 1024 / 32, B_), tb>>>(f4, 3, 1024, 144);

    k_select<<<1, B_>>>();
    k_compact<<<(B_ * N_ + 255) / 256, 256>>>();
    k_sort<<<B_, 512>>>(preds);
    k_iou<<<(B_ * KCAND * NW * 32) / 256, 256>>>();
    k_scan<<<B_, 512>>>();
    k_roi<<<B_ * NGRP, 128, ROI_SMEM_BYTES>>>(W1, b1, W2, b2, out);
}